// round 13
// baseline (speedup 1.0000x reference)
// NOTE (pitfall, R4): harness PTX target is sm_103 (no 'a') -> no tcgen05/TMEM.
// NOTE (pitfall, R3/R6/R8): do not restructure fragment LOADS (ldmatrix /
// LDS.64 repack all lost). Plain scalar C++ LDS inner loop is the optimum.
// R11: GEMM1 D-fragment == GEMM2 A-fragment (16x128 warp tile) -> register
// chain, no E2 smem round-trip, 2 barriers/tile.
#include <cuda_runtime.h>
#include <cuda_fp16.h>
#include <stdint.h>

#define H     128
#define CIN   64
#define NNODE 512
#define BATCH 2

// uint32 (=half2) strides, conflict-free per-fragment (validated R2/R5)
#define ESTRIDE 68    // E tile: 128 rows x 64 half2
#define WSTRIDE 136   // W tile: 64 kpair-rows x 128 n

// smem layout (bytes)
#define OFF_ES   0
#define SZ_ES    (128 * ESTRIDE * 4)             // 34816
#define OFF_W2   (OFF_ES + SZ_ES)                // 34816
#define SZ_W     (64 * WSTRIDE * 4)              // 34816
#define OFF_W3   (OFF_W2 + SZ_W)                 // 69632
#define OFF_BC2  (OFF_W3 + SZ_W)                 // 104448
#define OFF_BC3  (OFF_BC2 + 512)
#define OFF_WO   (OFF_BC3 + 512)
#define SMEM_BYTES (OFF_WO + 512)                // 105984

// scratch: u[b,n,k] = (relu-MLP h2)[b,n,:] @ Wc1  (fp32 + fp16 copies)
__device__ float  g_U [BATCH * NNODE * H];
__device__ __half g_Uh[BATCH * NNODE * H];

// ---------------------------------------------------------------------------
__device__ __forceinline__ uint32_t pack2(float a, float b) {
    __half2 h = __floats2half2_rn(a, b);
    return *reinterpret_cast<uint32_t*>(&h);
}

// relu(a + b) in packed half2
__device__ __forceinline__ uint32_t h2addrelu(uint32_t a, uint32_t b) {
    __half2 z = __float2half2_rn(0.f);
    __half2 r = __hmax2(__hadd2(*reinterpret_cast<__half2*>(&a),
                                *reinterpret_cast<__half2*>(&b)), z);
    return *reinterpret_cast<uint32_t*>(&r);
}

__device__ __forceinline__ void mma_f16(float c[4], const uint32_t a[4],
                                        uint32_t b0, uint32_t b1) {
    asm("mma.sync.aligned.m16n8k16.row.col.f32.f16.f16.f32 "
        "{%0,%1,%2,%3}, {%4,%5,%6,%7}, {%8,%9}, {%0,%1,%2,%3};"
        : "+f"(c[0]), "+f"(c[1]), "+f"(c[2]), "+f"(c[3])
        : "r"(a[0]), "r"(a[1]), "r"(a[2]), "r"(a[3]), "r"(b0), "r"(b1));
}

// ---------------------------------------------------------------------------
// stage 1: node MLP + u = h2 @ Wc1 (fp32 exact) + out=bo init (folded launch)
// ---------------------------------------------------------------------------
#define S1_NODES 4
__global__ __launch_bounds__(128) void stage1_kernel(
    const float* __restrict__ x,
    const float* __restrict__ Wa, const float* __restrict__ ba,
    const float* __restrict__ Wb, const float* __restrict__ bb,
    const float* __restrict__ Wc1,
    float* __restrict__ out, const float* __restrict__ bo) {
    __shared__ float xs[S1_NODES][CIN];
    __shared__ float h1s[S1_NODES][H + 4];
    __shared__ float h2s[S1_NODES][H + 4];
    int tid = threadIdx.x;
    int node0 = blockIdx.x * S1_NODES;

    // folded init: 32768 threads x 16 floats = 524288 = out_size
    {
        float v = bo[0];
        float4 vv = make_float4(v, v, v, v);
        float4* o4 = (float4*)out + (size_t)(blockIdx.x * 128 + tid) * 4;
        o4[0] = vv; o4[1] = vv; o4[2] = vv; o4[3] = vv;
    }

    for (int idx = tid; idx < S1_NODES * CIN; idx += 128)
        xs[idx / CIN][idx % CIN] = x[node0 * CIN + idx];
    __syncthreads();

    int k = tid;
    float acc[S1_NODES];
#pragma unroll
    for (int m = 0; m < S1_NODES; m++) acc[m] = ba[k];
#pragma unroll 8
    for (int c = 0; c < CIN; c++) {
        float w = Wa[c * H + k];
#pragma unroll
        for (int m = 0; m < S1_NODES; m++) acc[m] += xs[m][c] * w;
    }
#pragma unroll
    for (int m = 0; m < S1_NODES; m++) h1s[m][k] = fmaxf(acc[m], 0.f);
    __syncthreads();

#pragma unroll
    for (int m = 0; m < S1_NODES; m++) acc[m] = bb[k];
#pragma unroll 8
    for (int c = 0; c < H; c++) {
        float w = Wb[c * H + k];
#pragma unroll
        for (int m = 0; m < S1_NODES; m++) acc[m] += h1s[m][c] * w;
    }
#pragma unroll
    for (int m = 0; m < S1_NODES; m++) h2s[m][k] = fmaxf(acc[m], 0.f);
    __syncthreads();

#pragma unroll
    for (int m = 0; m < S1_NODES; m++) acc[m] = 0.f;
#pragma unroll 8
    for (int c = 0; c < H; c++) {
        float w = Wc1[c * H + k];
#pragma unroll
        for (int m = 0; m < S1_NODES; m++) acc[m] += h2s[m][c] * w;
    }
#pragma unroll
    for (int m = 0; m < S1_NODES; m++) {
        g_U [(node0 + m) * H + k] = acc[m];
        g_Uh[(node0 + m) * H + k] = __float2half(acc[m]);
    }
}

// ---------------------------------------------------------------------------
// stage 2: per-edge MLP. Warp tile 16(m)x128(n); Z2 stays in registers and
// feeds GEMM2 as A-fragments directly. 2 barriers/tile; GEMM2+epilogue of
// tile t overlap fill of tile t+1.
// ---------------------------------------------------------------------------
__global__ __launch_bounds__(256, 2) void stage2_kernel(
    const float* __restrict__ bc1,
    const float* __restrict__ Wc2, const float* __restrict__ bc2,
    const float* __restrict__ Wc3, const float* __restrict__ bc3,
    const float* __restrict__ Wo,
    float* __restrict__ out, int ntiles) {
    extern __shared__ unsigned char smem[];
    uint32_t* Es  = (uint32_t*)(smem + OFF_ES);
    uint32_t* W2s = (uint32_t*)(smem + OFF_W2);
    uint32_t* W3s = (uint32_t*)(smem + OFF_W3);
    float* bc2s = (float*)(smem + OFF_BC2);
    float* bc3s = (float*)(smem + OFF_BC3);
    float* wos  = (float*)(smem + OFF_WO);

    int tid = threadIdx.x;

    // one-time: stage weights as half2 (k-pair packed)
    for (int idx = tid; idx < 64 * H; idx += 256) {
        int kp = idx >> 7, n = idx & 127;
        W2s[kp * WSTRIDE + n] = pack2(Wc2[(2 * kp) * H + n], Wc2[(2 * kp + 1) * H + n]);
        W3s[kp * WSTRIDE + n] = pack2(Wc3[(2 * kp) * H + n], Wc3[(2 * kp + 1) * H + n]);
    }
    if (tid < H) {
        bc2s[tid] = bc2[tid];
        bc3s[tid] = bc3[tid];
        wos[tid]  = Wo[tid];
    }

    // fill mapping: thread owns 8 halves (cols cg*8..cg*8+7), rows rph+16it
    int cg  = tid & 15;
    int rph = tid >> 4;
    float4 b0f = ((const float4*)bc1)[cg * 2];
    float4 b1f = ((const float4*)bc1)[cg * 2 + 1];
    __syncthreads();

    int wid = tid >> 5, lane = tid & 31;
    int m_base = wid * 16;                 // warp owns rows m_base..m_base+15
    int qid = lane >> 2, tq = lane & 3;

    for (int t = blockIdx.x; t < ntiles; t += gridDim.x) {
        int jt = t & 3;
        int i  = (t >> 2) & (NNODE - 1);
        int b  = t >> 11;
        int j0 = jt << 7;

        // vcomb = bc1 - u_i (fp32, this thread's 8 cols) -> 4 half2
        const float4* Ui4 = (const float4*)(g_U + ((size_t)b * NNODE + i) * H + cg * 8);
        float4 u0 = Ui4[0], u1 = Ui4[1];
        uint32_t vc0 = pack2(b0f.x - u0.x, b0f.y - u0.y);
        uint32_t vc1 = pack2(b0f.z - u0.z, b0f.w - u0.w);
        uint32_t vc2 = pack2(b1f.x - u1.x, b1f.y - u1.y);
        uint32_t vc3 = pack2(b1f.z - u1.z, b1f.w - u1.w);

        // E1[j,k] = ReLU(u_j(h) + vc) in half2; 8 rows x 8 halves per thread
        const __half* Uj = g_Uh + ((size_t)b * NNODE + j0) * H + cg * 8;
#pragma unroll
        for (int it = 0; it < 8; it++) {
            int jj = rph + 16 * it;
            uint4 uh = *(const uint4*)(Uj + (size_t)jj * H);
            uint4 e;
            e.x = h2addrelu(uh.x, vc0);
            e.y = h2addrelu(uh.y, vc1);
            e.z = h2addrelu(uh.z, vc2);
            e.w = h2addrelu(uh.w, vc3);
            *(uint4*)(Es + jj * ESTRIDE + cg * 4) = e;
        }
        __syncthreads();  // (A) E1 ready

        // GEMM1: Z2[16x128] = E1[rows m_base..][:] @ Wc2  (acc in regs)
        float acc[16][4];
#pragma unroll
        for (int nt = 0; nt < 16; nt++)
#pragma unroll
            for (int q = 0; q < 4; q++) acc[nt][q] = 0.f;
#pragma unroll
        for (int k0 = 0; k0 < 64; k0 += 8) {
            const uint32_t* er = Es + (m_base + qid) * ESTRIDE + k0 + tq;
            uint32_t a[4];
            a[0] = er[0];
            a[1] = er[8 * ESTRIDE];
            a[2] = er[4];
            a[3] = er[8 * ESTRIDE + 4];
            const uint32_t* wr = W2s + (k0 + tq) * WSTRIDE + qid;
#pragma unroll
            for (int nt = 0; nt < 16; nt++) {
                uint32_t b0 = wr[nt * 8];
                uint32_t b1 = wr[4 * WSTRIDE + nt * 8];
                mma_f16(acc[nt], a, b0, b1);
            }
        }
        __syncthreads();  // (B) all Es reads done -> next fill may overwrite

        // E2 = ReLU(Z2 + bc2): D-fragment -> A-fragment, in registers
        uint32_t aF[8][4];
#pragma unroll
        for (int kk = 0; kk < 8; kk++) {
            int n0 = 16 * kk + 2 * tq;
            int n1 = n0 + 8;
            float c0 = bc2s[n0], c1 = bc2s[n0 + 1];
            float d0 = bc2s[n1], d1 = bc2s[n1 + 1];
            aF[kk][0] = pack2(fmaxf(acc[2 * kk][0] + c0, 0.f),
                              fmaxf(acc[2 * kk][1] + c1, 0.f));
            aF[kk][1] = pack2(fmaxf(acc[2 * kk][2] + c0, 0.f),
                              fmaxf(acc[2 * kk][3] + c1, 0.f));
            aF[kk][2] = pack2(fmaxf(acc[2 * kk + 1][0] + d0, 0.f),
                              fmaxf(acc[2 * kk + 1][1] + d1, 0.f));
            aF[kk][3] = pack2(fmaxf(acc[2 * kk + 1][2] + d0, 0.f),
                              fmaxf(acc[2 * kk + 1][3] + d1, 0.f));
        }

        // GEMM2: Z3 = E2 @ Wc3  (A from regs, B from static W3s)
        float acc2[16][4];
#pragma unroll
        for (int nt = 0; nt < 16; nt++)
#pragma unroll
            for (int q = 0; q < 4; q++) acc2[nt][q] = 0.f;
#pragma unroll
        for (int kk = 0; kk < 8; kk++) {
            const uint32_t* wr = W3s + (kk * 8 + tq) * WSTRIDE + qid;
#pragma unroll
            for (int nt = 0; nt < 16; nt++) {
                uint32_t b0 = wr[nt * 8];
                uint32_t b1 = wr[4 * WSTRIDE + nt * 8];
                mma_f16(acc2[nt], aF[kk], b0, b1);
            }
        }

        // epilogue: out[b,i,j0+row] += sum_n ReLU(Z3 + bc3) * Wo  (RED.GLOBAL)
        float* orow = out + ((size_t)b * NNODE + i) * NNODE + j0;
        {
            float s0 = 0.f, s1 = 0.f;
#pragma unroll
            for (int nt = 0; nt < 16; nt++) {
                int n = nt * 8 + 2 * tq;
                float c0 = bc3s[n], c1 = bc3s[n + 1];
                float w0 = wos[n],  w1 = wos[n + 1];
                s0 += fmaxf(acc2[nt][0] + c0, 0.f) * w0
                    + fmaxf(acc2[nt][1] + c1, 0.f) * w1;
                s1 += fmaxf(acc2[nt][2] + c0, 0.f) * w0
                    + fmaxf(acc2[nt][3] + c1, 0.f) * w1;
            }
            s0 += __shfl_xor_sync(0xffffffffu, s0, 1);
            s0 += __shfl_xor_sync(0xffffffffu, s0, 2);
            s1 += __shfl_xor_sync(0xffffffffu, s1, 1);
            s1 += __shfl_xor_sync(0xffffffffu, s1, 2);
            if (tq == 0) {
                atomicAdd(orow + m_base + qid, s0);
                atomicAdd(orow + m_base + qid + 8, s1);
            }
        }
        // no further sync: GEMM2/epilogue touch only regs/W3s/out, so the
        // next tile's fill (after its own sync A) cannot race Es reads.
    }
}

// ---------------------------------------------------------------------------
extern "C" void kernel_launch(void* const* d_in, const int* in_sizes, int n_in,
                              void* d_out, int out_size) {
    const float* x   = (const float*)d_in[0];
    const float* Wa  = (const float*)d_in[1];
    const float* ba  = (const float*)d_in[2];
    const float* Wb  = (const float*)d_in[3];
    const float* bb  = (const float*)d_in[4];
    const float* Wc1 = (const float*)d_in[5];
    const float* bc1 = (const float*)d_in[6];
    const float* Wc2 = (const float*)d_in[7];
    const float* bc2 = (const float*)d_in[8];
    const float* Wc3 = (const float*)d_in[9];
    const float* bc3 = (const float*)d_in[10];
    const float* Wo  = (const float*)d_in[11];
    const float* bo  = (const float*)d_in[12];
    float* out = (float*)d_out;

    cudaFuncSetAttribute(stage2_kernel,
                         cudaFuncAttributeMaxDynamicSharedMemorySize, SMEM_BYTES);

    stage1_kernel<<<(BATCH * NNODE) / S1_NODES, 128>>>(x, Wa, ba, Wb, bb, Wc1,
                                                       out, bo);

    int ntiles = BATCH * NNODE * (NNODE / 128);  // 4096
    stage2_kernel<<<304, 256, SMEM_BYTES>>>(bc1, Wc2, bc2, Wc3, bc3, Wo,
                                            out, ntiles);
}

// round 14
// speedup vs baseline: 1.0208x; 1.0208x over previous
// NOTE (pitfall, R4): harness PTX target is sm_103 (no 'a') -> no tcgen05/TMEM.
// NOTE (pitfall, R3/R6/R8): do not restructure fragment LOADS. Plain scalar
// C++ LDS inner loop is the optimum.
// NOTE (R11): tensor floor ~56us is fixed; optimize OVERLAP of the rest.
// R13: two independent 4-warp streams per CTA (named barriers, split Es).
#include <cuda_runtime.h>
#include <cuda_fp16.h>
#include <stdint.h>

#define H     128
#define CIN   64
#define NNODE 512
#define BATCH 2

// uint32 (=half2) strides, conflict-free per-fragment (validated R2/R5)
#define ESTRIDE 68    // E half-tile: 64 rows x 64 half2
#define WSTRIDE 136   // W tile: 64 kpair-rows x 128 n

// smem layout (bytes)
#define OFF_ES   0                               // 2 half-tile buffers
#define SZ_EH    (64 * ESTRIDE * 4)              // 17408 per half
#define OFF_W2   (OFF_ES + 2 * SZ_EH)            // 34816
#define SZ_W     (64 * WSTRIDE * 4)              // 34816
#define OFF_W3   (OFF_W2 + SZ_W)                 // 69632
#define OFF_BC2  (OFF_W3 + SZ_W)                 // 104448
#define OFF_BC3  (OFF_BC2 + 512)
#define OFF_WO   (OFF_BC3 + 512)
#define SMEM_BYTES (OFF_WO + 512)                // 105984

// scratch: u[b,n,k] = (relu-MLP h2)[b,n,:] @ Wc1  (fp32 + fp16 copies)
__device__ float  g_U [BATCH * NNODE * H];
__device__ __half g_Uh[BATCH * NNODE * H];

// ---------------------------------------------------------------------------
__device__ __forceinline__ uint32_t pack2(float a, float b) {
    __half2 h = __floats2half2_rn(a, b);
    return *reinterpret_cast<uint32_t*>(&h);
}

// relu(a + b) in packed half2
__device__ __forceinline__ uint32_t h2addrelu(uint32_t a, uint32_t b) {
    __half2 z = __float2half2_rn(0.f);
    __half2 r = __hmax2(__hadd2(*reinterpret_cast<__half2*>(&a),
                                *reinterpret_cast<__half2*>(&b)), z);
    return *reinterpret_cast<uint32_t*>(&r);
}

__device__ __forceinline__ void mma_f16(float c[4], const uint32_t a[4],
                                        uint32_t b0, uint32_t b1) {
    asm("mma.sync.aligned.m16n8k16.row.col.f32.f16.f16.f32 "
        "{%0,%1,%2,%3}, {%4,%5,%6,%7}, {%8,%9}, {%0,%1,%2,%3};"
        : "+f"(c[0]), "+f"(c[1]), "+f"(c[2]), "+f"(c[3])
        : "r"(a[0]), "r"(a[1]), "r"(a[2]), "r"(a[3]), "r"(b0), "r"(b1));
}

// half-stream barrier: id 1 or 2, 128 threads
__device__ __forceinline__ void barh(int id) {
    asm volatile("bar.sync %0, 128;" :: "r"(id) : "memory");
}

// 64x128x128 fp16 GEMM (one half-stream, 4 warps, warp tile 32x64).
// Identical per-warp load/MMA structure to the validated R9 loop.
__device__ __forceinline__ void gemm64h(const uint32_t* __restrict__ Es,
                                        const uint32_t* __restrict__ Ws,
                                        float acc[2][8][4],
                                        int m_base, int n_base, int qid, int tq) {
#pragma unroll
    for (int k0 = 0; k0 < 64; k0 += 8) {   // k0 in half2 units (16 halves/step)
        uint32_t a[2][4];
#pragma unroll
        for (int mt = 0; mt < 2; mt++) {
            const uint32_t* er = Es + (m_base + mt * 16 + qid) * ESTRIDE + k0 + tq;
            a[mt][0] = er[0];
            a[mt][1] = er[8 * ESTRIDE];
            a[mt][2] = er[4];
            a[mt][3] = er[8 * ESTRIDE + 4];
        }
        const uint32_t* wr = Ws + (k0 + tq) * WSTRIDE + n_base + qid;
#pragma unroll
        for (int nt = 0; nt < 8; nt++) {
            uint32_t b0 = wr[nt * 8];
            uint32_t b1 = wr[4 * WSTRIDE + nt * 8];
            mma_f16(acc[0][nt], a[0], b0, b1);
            mma_f16(acc[1][nt], a[1], b0, b1);
        }
    }
}

// ---------------------------------------------------------------------------
// stage 1: node MLP + u = h2 @ Wc1 (fp32 exact) + out=bo init (folded launch)
// ---------------------------------------------------------------------------
#define S1_NODES 4
__global__ __launch_bounds__(128) void stage1_kernel(
    const float* __restrict__ x,
    const float* __restrict__ Wa, const float* __restrict__ ba,
    const float* __restrict__ Wb, const float* __restrict__ bb,
    const float* __restrict__ Wc1,
    float* __restrict__ out, const float* __restrict__ bo) {
    __shared__ float xs[S1_NODES][CIN];
    __shared__ float h1s[S1_NODES][H + 4];
    __shared__ float h2s[S1_NODES][H + 4];
    int tid = threadIdx.x;
    int node0 = blockIdx.x * S1_NODES;

    // folded init: 32768 threads x 16 floats = 524288 = out_size
    {
        float v = bo[0];
        float4 vv = make_float4(v, v, v, v);
        float4* o4 = (float4*)out + (size_t)(blockIdx.x * 128 + tid) * 4;
        o4[0] = vv; o4[1] = vv; o4[2] = vv; o4[3] = vv;
    }

    for (int idx = tid; idx < S1_NODES * CIN; idx += 128)
        xs[idx / CIN][idx % CIN] = x[node0 * CIN + idx];
    __syncthreads();

    int k = tid;
    float acc[S1_NODES];
#pragma unroll
    for (int m = 0; m < S1_NODES; m++) acc[m] = ba[k];
#pragma unroll 8
    for (int c = 0; c < CIN; c++) {
        float w = Wa[c * H + k];
#pragma unroll
        for (int m = 0; m < S1_NODES; m++) acc[m] += xs[m][c] * w;
    }
#pragma unroll
    for (int m = 0; m < S1_NODES; m++) h1s[m][k] = fmaxf(acc[m], 0.f);
    __syncthreads();

#pragma unroll
    for (int m = 0; m < S1_NODES; m++) acc[m] = bb[k];
#pragma unroll 8
    for (int c = 0; c < H; c++) {
        float w = Wb[c * H + k];
#pragma unroll
        for (int m = 0; m < S1_NODES; m++) acc[m] += h1s[m][c] * w;
    }
#pragma unroll
    for (int m = 0; m < S1_NODES; m++) h2s[m][k] = fmaxf(acc[m], 0.f);
    __syncthreads();

#pragma unroll
    for (int m = 0; m < S1_NODES; m++) acc[m] = 0.f;
#pragma unroll 8
    for (int c = 0; c < H; c++) {
        float w = Wc1[c * H + k];
#pragma unroll
        for (int m = 0; m < S1_NODES; m++) acc[m] += h2s[m][c] * w;
    }
#pragma unroll
    for (int m = 0; m < S1_NODES; m++) {
        g_U [(node0 + m) * H + k] = acc[m];
        g_Uh[(node0 + m) * H + k] = __float2half(acc[m]);
    }
}

// ---------------------------------------------------------------------------
// stage 2: per-edge MLP. Two independent 4-warp streams per CTA, each with
// its own 64-row j-tile, Es buffer, and named barrier. 8192 tiles total.
// ---------------------------------------------------------------------------
__global__ __launch_bounds__(256, 2) void stage2_kernel(
    const float* __restrict__ bc1,
    const float* __restrict__ Wc2, const float* __restrict__ bc2,
    const float* __restrict__ Wc3, const float* __restrict__ bc3,
    const float* __restrict__ Wo,
    float* __restrict__ out, int ntiles, int nstreams) {
    extern __shared__ unsigned char smem[];
    uint32_t* W2s = (uint32_t*)(smem + OFF_W2);
    uint32_t* W3s = (uint32_t*)(smem + OFF_W3);
    float* bc2s = (float*)(smem + OFF_BC2);
    float* bc3s = (float*)(smem + OFF_BC3);
    float* wos  = (float*)(smem + OFF_WO);

    int tid = threadIdx.x;

    // one-time: stage weights as half2 (k-pair packed); whole CTA cooperates
    for (int idx = tid; idx < 64 * H; idx += 256) {
        int kp = idx >> 7, n = idx & 127;
        W2s[kp * WSTRIDE + n] = pack2(Wc2[(2 * kp) * H + n], Wc2[(2 * kp + 1) * H + n]);
        W3s[kp * WSTRIDE + n] = pack2(Wc3[(2 * kp) * H + n], Wc3[(2 * kp + 1) * H + n]);
    }
    if (tid < H) {
        bc2s[tid] = bc2[tid];
        bc3s[tid] = bc3[tid];
        wos[tid]  = Wo[tid];
    }
    __syncthreads();   // after this, streams are independent

    int half = tid >> 7;                    // 0 or 1
    int ltid = tid & 127;                   // tid within stream
    int bar  = half + 1;                    // named barrier id
    uint32_t* Es = (uint32_t*)(smem + OFF_ES + half * SZ_EH);

    // fill mapping: thread owns 8 halves (cols cg*8..+7), rows rph + 8*it
    int cg  = ltid & 15;
    int rph = ltid >> 4;                    // 0..7
    float4 b0f = ((const float4*)bc1)[cg * 2];
    float4 b1f = ((const float4*)bc1)[cg * 2 + 1];

    int wid2 = (ltid >> 5) & 3, lane = ltid & 31;
    int wm = wid2 >> 1, wn = wid2 & 1;
    int m_base = wm * 32, n_base = wn * 64;
    int qid = lane >> 2, tq = lane & 3;

    const float2* bc2p = (const float2*)bc2s;
    const float2* bc3p = (const float2*)bc3s;
    const float2* wop  = (const float2*)wos;

    for (int t = blockIdx.x * 2 + half; t < ntiles; t += nstreams) {
        int jt = t & 7;
        int i  = (t >> 3) & (NNODE - 1);
        int b  = t >> 12;
        int j0 = jt << 6;

        // vcomb = bc1 - u_i (fp32, this thread's 8 cols) -> 4 half2
        const float4* Ui4 = (const float4*)(g_U + ((size_t)b * NNODE + i) * H + cg * 8);
        float4 u0 = Ui4[0], u1 = Ui4[1];
        uint32_t vc0 = pack2(b0f.x - u0.x, b0f.y - u0.y);
        uint32_t vc1 = pack2(b0f.z - u0.z, b0f.w - u0.w);
        uint32_t vc2 = pack2(b1f.x - u1.x, b1f.y - u1.y);
        uint32_t vc3 = pack2(b1f.z - u1.z, b1f.w - u1.w);

        // E1[j,k] = ReLU(u_j(h) + vc); 8 rows x 8 halves per thread
        const __half* Uj = g_Uh + ((size_t)b * NNODE + j0) * H + cg * 8;
#pragma unroll
        for (int it = 0; it < 8; it++) {
            int jj = rph + 8 * it;
            uint4 uh = *(const uint4*)(Uj + (size_t)jj * H);
            uint4 e;
            e.x = h2addrelu(uh.x, vc0);
            e.y = h2addrelu(uh.y, vc1);
            e.z = h2addrelu(uh.z, vc2);
            e.w = h2addrelu(uh.w, vc3);
            *(uint4*)(Es + jj * ESTRIDE + cg * 4) = e;
        }
        barh(bar);  // (A) E1 ready

        // GEMM1: Z2 = E1 @ Wc2
        float acc[2][8][4];
#pragma unroll
        for (int mt = 0; mt < 2; mt++)
#pragma unroll
            for (int nt = 0; nt < 8; nt++)
#pragma unroll
                for (int q = 0; q < 4; q++) acc[mt][nt][q] = 0.f;
        gemm64h(Es, W2s, acc, m_base, n_base, qid, tq);
        barh(bar);  // (B) E1 reads done

        // E2 = ReLU(Z2 + bc2) -> half2 back into Es
#pragma unroll
        for (int mt = 0; mt < 2; mt++) {
            int r = m_base + mt * 16 + qid;
#pragma unroll
            for (int nt = 0; nt < 8; nt++) {
                int n  = n_base + nt * 8 + 2 * tq;
                int np = n >> 1;
                float2 c = bc2p[np];
                Es[r * ESTRIDE + np] =
                    pack2(fmaxf(acc[mt][nt][0] + c.x, 0.f),
                          fmaxf(acc[mt][nt][1] + c.y, 0.f));
                Es[(r + 8) * ESTRIDE + np] =
                    pack2(fmaxf(acc[mt][nt][2] + c.x, 0.f),
                          fmaxf(acc[mt][nt][3] + c.y, 0.f));
            }
        }
        barh(bar);  // (C) E2 ready

        // GEMM2: Z3 = E2 @ Wc3
#pragma unroll
        for (int mt = 0; mt < 2; mt++)
#pragma unroll
            for (int nt = 0; nt < 8; nt++)
#pragma unroll
                for (int q = 0; q < 4; q++) acc[mt][nt][q] = 0.f;
        gemm64h(Es, W3s, acc, m_base, n_base, qid, tq);
        barh(bar);  // (D) E2 reads done -> next fill may overwrite

        // epilogue: out[b,i,j0+row] += sum_n ReLU(Z3 + bc3) * Wo  (RED.GLOBAL)
        float* orow = out + ((size_t)b * NNODE + i) * NNODE + j0;
#pragma unroll
        for (int mt = 0; mt < 2; mt++) {
            float s0e = 0.f, s1e = 0.f;
#pragma unroll
            for (int nt = 0; nt < 8; nt++) {
                int np = (n_base + nt * 8 + 2 * tq) >> 1;
                float2 c = bc3p[np];
                float2 w = wop[np];
                s0e += fmaxf(acc[mt][nt][0] + c.x, 0.f) * w.x
                     + fmaxf(acc[mt][nt][1] + c.y, 0.f) * w.y;
                s1e += fmaxf(acc[mt][nt][2] + c.x, 0.f) * w.x
                     + fmaxf(acc[mt][nt][3] + c.y, 0.f) * w.y;
            }
            s0e += __shfl_xor_sync(0xffffffffu, s0e, 1);
            s0e += __shfl_xor_sync(0xffffffffu, s0e, 2);
            s1e += __shfl_xor_sync(0xffffffffu, s1e, 1);
            s1e += __shfl_xor_sync(0xffffffffu, s1e, 2);
            if (tq == 0) {
                atomicAdd(orow + m_base + mt * 16 + qid, s0e);
                atomicAdd(orow + m_base + mt * 16 + qid + 8, s1e);
            }
        }
    }
}

// ---------------------------------------------------------------------------
extern "C" void kernel_launch(void* const* d_in, const int* in_sizes, int n_in,
                              void* d_out, int out_size) {
    const float* x   = (const float*)d_in[0];
    const float* Wa  = (const float*)d_in[1];
    const float* ba  = (const float*)d_in[2];
    const float* Wb  = (const float*)d_in[3];
    const float* bb  = (const float*)d_in[4];
    const float* Wc1 = (const float*)d_in[5];
    const float* bc1 = (const float*)d_in[6];
    const float* Wc2 = (const float*)d_in[7];
    const float* bc2 = (const float*)d_in[8];
    const float* Wc3 = (const float*)d_in[9];
    const float* bc3 = (const float*)d_in[10];
    const float* Wo  = (const float*)d_in[11];
    const float* bo  = (const float*)d_in[12];
    float* out = (float*)d_out;

    cudaFuncSetAttribute(stage2_kernel,
                         cudaFuncAttributeMaxDynamicSharedMemorySize, SMEM_BYTES);

    stage1_kernel<<<(BATCH * NNODE) / S1_NODES, 128>>>(x, Wa, ba, Wb, bb, Wc1,
                                                       out, bo);

    int ntiles = BATCH * NNODE * (NNODE / 64);   // 8192
    int grid = 304;
    stage2_kernel<<<grid, 256, SMEM_BYTES>>>(bc1, Wc2, bc2, Wc3, bc3, Wo,
                                             out, ntiles, grid * 2);
}

// round 17
// speedup vs baseline: 1.0957x; 1.0734x over previous
// NOTE (pitfall, R4): harness PTX target is sm_103 (no 'a') -> no tcgen05/TMEM.
// NOTE (pitfall, R3/R6/R8): do not restructure fragment LOADS. Plain scalar
// C++ LDS inner loop is the optimum.
// NOTE (R11/R13): stage2 structure is at its optimum (~105us).
// R14 bug: epilogue dropped the mt*16 row term -> fixed here (R15).
#include <cuda_runtime.h>
#include <cuda_fp16.h>
#include <stdint.h>

#define H     128
#define CIN   64
#define NNODE 512
#define BATCH 2
#define GRID  304
#define NTILES 4096

// uint32 (=half2) strides, conflict-free per-fragment (validated R2/R5)
#define ESTRIDE 68    // E tile: 128 rows x 64 half2
#define WSTRIDE 136   // W tile: 64 kpair-rows x 128 n

// smem layout (bytes)
#define OFF_ES   0
#define SZ_ES    (128 * ESTRIDE * 4)             // 34816
#define OFF_W2   (OFF_ES + SZ_ES)                // 34816
#define SZ_W     (64 * WSTRIDE * 4)              // 34816
#define OFF_W3   (OFF_W2 + SZ_W)                 // 69632
#define OFF_BC2  (OFF_W3 + SZ_W)                 // 104448
#define OFF_BC3  (OFF_BC2 + 512)
#define OFF_WO   (OFF_BC3 + 512)
#define SMEM_BYTES (OFF_WO + 512)                // 105984

// scratch: u[b,n,k] = (relu-MLP h2)[b,n,:] @ Wc1  (fp32 + fp16 copies)
__device__ float  g_U [BATCH * NNODE * H];
__device__ __half g_Uh[BATCH * NNODE * H];
__device__ int    g_ctr;   // monotonic epoch counter (never reset; replay-safe)

// ---------------------------------------------------------------------------
__device__ __forceinline__ uint32_t pack2(float a, float b) {
    __half2 h = __floats2half2_rn(a, b);
    return *reinterpret_cast<uint32_t*>(&h);
}

// relu(a + b) in packed half2
__device__ __forceinline__ uint32_t h2addrelu(uint32_t a, uint32_t b) {
    __half2 z = __float2half2_rn(0.f);
    __half2 r = __hmax2(__hadd2(*reinterpret_cast<__half2*>(&a),
                                *reinterpret_cast<__half2*>(&b)), z);
    return *reinterpret_cast<uint32_t*>(&r);
}

__device__ __forceinline__ void mma_f16(float c[4], const uint32_t a[4],
                                        uint32_t b0, uint32_t b1) {
    asm("mma.sync.aligned.m16n8k16.row.col.f32.f16.f16.f32 "
        "{%0,%1,%2,%3}, {%4,%5,%6,%7}, {%8,%9}, {%0,%1,%2,%3};"
        : "+f"(c[0]), "+f"(c[1]), "+f"(c[2]), "+f"(c[3])
        : "r"(a[0]), "r"(a[1]), "r"(a[2]), "r"(a[3]), "r"(b0), "r"(b1));
}

// 128x128x128 fp16 GEMM — validated optimum, DO NOT MODIFY.
__device__ __forceinline__ void gemm128h(const uint32_t* __restrict__ Es,
                                         const uint32_t* __restrict__ Ws,
                                         float acc[2][8][4],
                                         int m_base, int n_base, int qid, int tq) {
#pragma unroll
    for (int k0 = 0; k0 < 64; k0 += 8) {
        uint32_t a[2][4];
#pragma unroll
        for (int mt = 0; mt < 2; mt++) {
            const uint32_t* er = Es + (m_base + mt * 16 + qid) * ESTRIDE + k0 + tq;
            a[mt][0] = er[0];
            a[mt][1] = er[8 * ESTRIDE];
            a[mt][2] = er[4];
            a[mt][3] = er[8 * ESTRIDE + 4];
        }
        const uint32_t* wr = Ws + (k0 + tq) * WSTRIDE + n_base + qid;
#pragma unroll
        for (int nt = 0; nt < 8; nt++) {
            uint32_t b0 = wr[nt * 8];
            uint32_t b1 = wr[4 * WSTRIDE + nt * 8];
            mma_f16(acc[0][nt], a[0], b0, b1);
            mma_f16(acc[1][nt], a[1], b0, b1);
        }
    }
}

// ---------------------------------------------------------------------------
// fused kernel: out-init + node-MLP U slice + epoch grid-barrier + edge MLP
// ---------------------------------------------------------------------------
#define S1_NODES 4
__global__ __launch_bounds__(256, 2) void fused_kernel(
    const float* __restrict__ x,
    const float* __restrict__ Wa, const float* __restrict__ ba,
    const float* __restrict__ Wb, const float* __restrict__ bb,
    const float* __restrict__ Wc1, const float* __restrict__ bc1,
    const float* __restrict__ Wc2, const float* __restrict__ bc2,
    const float* __restrict__ Wc3, const float* __restrict__ bc3,
    const float* __restrict__ Wo, const float* __restrict__ bo,
    float* __restrict__ out) {
    extern __shared__ unsigned char smem[];
    uint32_t* Es  = (uint32_t*)(smem + OFF_ES);
    uint32_t* W2s = (uint32_t*)(smem + OFF_W2);
    uint32_t* W3s = (uint32_t*)(smem + OFF_W3);
    float* bc2s = (float*)(smem + OFF_BC2);
    float* bc3s = (float*)(smem + OFF_BC3);
    float* wos  = (float*)(smem + OFF_WO);

    int tid = threadIdx.x;
    int bid = blockIdx.x;

    // ---- phase 0a: stage weights as half2 (independent of U) ----
    for (int idx = tid; idx < 64 * H; idx += 256) {
        int kp = idx >> 7, n = idx & 127;
        W2s[kp * WSTRIDE + n] = pack2(Wc2[(2 * kp) * H + n], Wc2[(2 * kp + 1) * H + n]);
        W3s[kp * WSTRIDE + n] = pack2(Wc3[(2 * kp) * H + n], Wc3[(2 * kp + 1) * H + n]);
    }
    if (tid < H) {
        bc2s[tid] = bc2[tid];
        bc3s[tid] = bc3[tid];
        wos[tid]  = Wo[tid];
    }

    // ---- phase 0b: out = bo (must precede barrier; epilogue uses RED.ADD) ----
    {
        float v = bo[0];
        float4 vv = make_float4(v, v, v, v);
        float4* o4 = (float4*)out;
        for (int idx = bid * 256 + tid; idx < (BATCH * NNODE * NNODE) / 4;
             idx += GRID * 256)
            o4[idx] = vv;
    }

    // ---- phase 1: U slice (first 256 CTAs, 4 nodes each); Es = scratch ----
    if (bid < (BATCH * NNODE) / S1_NODES) {
        float* sc_x  = (float*)Es;                       // [4][64]
        float* sc_h1 = sc_x + S1_NODES * CIN;            // [4][132]
        float* sc_h2 = sc_h1 + S1_NODES * (H + 4);       // [4][132]
        int node0 = bid * S1_NODES;

        for (int idx = tid; idx < S1_NODES * CIN; idx += 256)
            sc_x[idx] = x[node0 * CIN + idx];
        __syncthreads();

        if (tid < H) {
            int k = tid;
            float acc[S1_NODES];
#pragma unroll
            for (int m = 0; m < S1_NODES; m++) acc[m] = ba[k];
#pragma unroll 8
            for (int c = 0; c < CIN; c++) {
                float w = Wa[c * H + k];
#pragma unroll
                for (int m = 0; m < S1_NODES; m++) acc[m] += sc_x[m * CIN + c] * w;
            }
#pragma unroll
            for (int m = 0; m < S1_NODES; m++)
                sc_h1[m * (H + 4) + k] = fmaxf(acc[m], 0.f);
        }
        __syncthreads();

        if (tid < H) {
            int k = tid;
            float acc[S1_NODES];
#pragma unroll
            for (int m = 0; m < S1_NODES; m++) acc[m] = bb[k];
#pragma unroll 8
            for (int c = 0; c < H; c++) {
                float w = Wb[c * H + k];
#pragma unroll
                for (int m = 0; m < S1_NODES; m++)
                    acc[m] += sc_h1[m * (H + 4) + c] * w;
            }
#pragma unroll
            for (int m = 0; m < S1_NODES; m++)
                sc_h2[m * (H + 4) + k] = fmaxf(acc[m], 0.f);
        }
        __syncthreads();

        if (tid < H) {
            int k = tid;
            float acc[S1_NODES];
#pragma unroll
            for (int m = 0; m < S1_NODES; m++) acc[m] = 0.f;
#pragma unroll 8
            for (int c = 0; c < H; c++) {
                float w = Wc1[c * H + k];
#pragma unroll
                for (int m = 0; m < S1_NODES; m++)
                    acc[m] += sc_h2[m * (H + 4) + c] * w;
            }
#pragma unroll
            for (int m = 0; m < S1_NODES; m++) {
                g_U [(node0 + m) * H + k] = acc[m];
                g_Uh[(node0 + m) * H + k] = __float2half(acc[m]);
            }
        }
        __syncthreads();   // Es scratch free before main loop
    }

    // ---- grid barrier: epoch counter (monotonic; graph-replay-safe) ----
    __threadfence();
    __syncthreads();
    if (tid == 0) {
        int old = atomicAdd(&g_ctr, 1);
        int target = (old / GRID + 1) * GRID;
        while (*(volatile int*)&g_ctr < target) { }
        __threadfence();
    }
    __syncthreads();

    // ---- phase 2: edge MLP (identical to validated 104.7us loop) ----
    int cg  = tid & 15;
    int rph = tid >> 4;
    float4 b0f = ((const float4*)bc1)[cg * 2];
    float4 b1f = ((const float4*)bc1)[cg * 2 + 1];

    int warp = tid >> 5, lane = tid & 31;
    int wm = warp >> 1, wn = warp & 1;
    int m_base = wm * 32, n_base = wn * 64;
    int qid = lane >> 2, tq = lane & 3;

    for (int t = bid; t < NTILES; t += GRID) {
        int jt = t & 3;
        int i  = (t >> 2) & (NNODE - 1);
        int b  = t >> 11;
        int j0 = jt << 7;

        // vcomb = bc1 - u_i (fp32, this thread's 8 cols) -> 4 half2
        const float4* Ui4 = (const float4*)(g_U + ((size_t)b * NNODE + i) * H + cg * 8);
        float4 u0 = Ui4[0], u1 = Ui4[1];
        uint32_t vc0 = pack2(b0f.x - u0.x, b0f.y - u0.y);
        uint32_t vc1 = pack2(b0f.z - u0.z, b0f.w - u0.w);
        uint32_t vc2 = pack2(b1f.x - u1.x, b1f.y - u1.y);
        uint32_t vc3 = pack2(b1f.z - u1.z, b1f.w - u1.w);

        // E1[j,k] = ReLU(u_j(h) + vc) in half2; 8 rows x 8 halves per thread
        const __half* Uj = g_Uh + ((size_t)b * NNODE + j0) * H + cg * 8;
#pragma unroll
        for (int it = 0; it < 8; it++) {
            int jj = rph + 16 * it;
            uint4 uh = *(const uint4*)(Uj + (size_t)jj * H);
            uint4 e;
            e.x = h2addrelu(uh.x, vc0);
            e.y = h2addrelu(uh.y, vc1);
            e.z = h2addrelu(uh.z, vc2);
            e.w = h2addrelu(uh.w, vc3);
            *(uint4*)(Es + jj * ESTRIDE + cg * 4) = e;
        }
        __syncthreads();  // (A) E1 ready

        // GEMM1: Z2 = E1 @ Wc2
        float acc[2][8][4];
#pragma unroll
        for (int mt = 0; mt < 2; mt++)
#pragma unroll
            for (int nt = 0; nt < 8; nt++)
#pragma unroll
                for (int q = 0; q < 4; q++) acc[mt][nt][q] = 0.f;
        gemm128h(Es, W2s, acc, m_base, n_base, qid, tq);
        __syncthreads();  // (B) E1 reads done

        // E2 = ReLU(Z2 + bc2) -> half2 back into Es
#pragma unroll
        for (int mt = 0; mt < 2; mt++) {
            int r = m_base + mt * 16 + qid;
#pragma unroll
            for (int nt = 0; nt < 8; nt++) {
                int n  = n_base + nt * 8 + 2 * tq;
                int np = n >> 1;
                Es[r * ESTRIDE + np] =
                    pack2(fmaxf(acc[mt][nt][0] + bc2s[n], 0.f),
                          fmaxf(acc[mt][nt][1] + bc2s[n + 1], 0.f));
                Es[(r + 8) * ESTRIDE + np] =
                    pack2(fmaxf(acc[mt][nt][2] + bc2s[n], 0.f),
                          fmaxf(acc[mt][nt][3] + bc2s[n + 1], 0.f));
            }
        }
        __syncthreads();  // (C) E2 ready

        // GEMM2: Z3 = E2 @ Wc3
#pragma unroll
        for (int mt = 0; mt < 2; mt++)
#pragma unroll
            for (int nt = 0; nt < 8; nt++)
#pragma unroll
                for (int q = 0; q < 4; q++) acc[mt][nt][q] = 0.f;
        gemm128h(Es, W3s, acc, m_base, n_base, qid, tq);
        __syncthreads();  // (D) E2 reads done -> next fill may overwrite

        // epilogue: out[b,i,j0+row] += sum_n ReLU(Z3 + bc3) * Wo  (RED.GLOBAL)
        float* orow = out + ((size_t)b * NNODE + i) * NNODE + j0;
#pragma unroll
        for (int mt = 0; mt < 2; mt++) {
            float s0e = 0.f, s1e = 0.f;
#pragma unroll
            for (int nt = 0; nt < 8; nt++) {
                int n = n_base + nt * 8 + 2 * tq;
                s0e += fmaxf(acc[mt][nt][0] + bc3s[n], 0.f) * wos[n]
                     + fmaxf(acc[mt][nt][1] + bc3s[n + 1], 0.f) * wos[n + 1];
                s1e += fmaxf(acc[mt][nt][2] + bc3s[n], 0.f) * wos[n]
                     + fmaxf(acc[mt][nt][3] + bc3s[n + 1], 0.f) * wos[n + 1];
            }
            s0e += __shfl_xor_sync(0xffffffffu, s0e, 1);
            s0e += __shfl_xor_sync(0xffffffffu, s0e, 2);
            s1e += __shfl_xor_sync(0xffffffffu, s1e, 1);
            s1e += __shfl_xor_sync(0xffffffffu, s1e, 2);
            if (tq == 0) {
                atomicAdd(orow + m_base + mt * 16 + qid, s0e);      // R15 fix
                atomicAdd(orow + m_base + mt * 16 + qid + 8, s1e);  // R15 fix
            }
        }
    }
}

// ---------------------------------------------------------------------------
extern "C" void kernel_launch(void* const* d_in, const int* in_sizes, int n_in,
                              void* d_out, int out_size) {
    const float* x   = (const float*)d_in[0];
    const float* Wa  = (const float*)d_in[1];
    const float* ba  = (const float*)d_in[2];
    const float* Wb  = (const float*)d_in[3];
    const float* bb  = (const float*)d_in[4];
    const float* Wc1 = (const float*)d_in[5];
    const float* bc1 = (const float*)d_in[6];
    const float* Wc2 = (const float*)d_in[7];
    const float* bc2 = (const float*)d_in[8];
    const float* Wc3 = (const float*)d_in[9];
    const float* bc3 = (const float*)d_in[10];
    const float* Wo  = (const float*)d_in[11];
    const float* bo  = (const float*)d_in[12];
    float* out = (float*)d_out;

    cudaFuncSetAttribute(fused_kernel,
                         cudaFuncAttributeMaxDynamicSharedMemorySize, SMEM_BYTES);

    fused_kernel<<<GRID, 256, SMEM_BYTES>>>(x, Wa, ba, Wb, bb, Wc1, bc1,
                                            Wc2, bc2, Wc3, bc3, Wo, bo, out);
}